// round 3
// baseline (speedup 1.0000x reference)
#include <cuda_runtime.h>
#include <math.h>

#define D 128
#define MAXN 100096
#define MAXE 1600256
#define EPSL 1e-5f
#define ROWS 64
#define THREADS 256

typedef unsigned long long ull;

__device__ __forceinline__ void ffma2(ull &d, ull a, ull b) {
    asm("fma.rn.f32x2 %0, %1, %2, %0;" : "+l"(d) : "l"(a), "l"(b));
}
__device__ __forceinline__ float2 unpack2(ull v) {
    float2 f; asm("mov.b64 {%0, %1}, %2;" : "=f"(f.x), "=f"(f.y) : "l"(v)); return f;
}

// ---------------- scratch (device globals: no allocation allowed) ----------------
__device__ float g_res[(size_t)MAXN * D];
__device__ float g_h0 [(size_t)MAXN * D];
__device__ float g_h1 [(size_t)MAXN * D];
__device__ float g_invdeg[MAXN];
__device__ int   g_deg[MAXN];
__device__ int   g_rowptr[MAXN + 1];
__device__ int   g_cursor[MAXN];
__device__ int   g_scantmp[MAXN];
__device__ int   g_blksums[256];
__device__ int   g_srcsorted[MAXE];

// ---------------- CSR build ----------------
__global__ void k_zero(int* deg, int* rowptr, int N) {
    int i = blockIdx.x * blockDim.x + threadIdx.x;
    if (i < N) deg[i] = 0;
    if (i == 0) rowptr[0] = 0;
}

__global__ void k_count(const int* __restrict__ dst, int* __restrict__ deg, int E) {
    int e = blockIdx.x * blockDim.x + threadIdx.x;
    if (e < E) atomicAdd(&deg[dst[e]], 1);
}

__global__ void k_scan1(const int* __restrict__ deg, int* __restrict__ tmp,
                        int* __restrict__ blks, int N) {
    __shared__ int sm[1024];
    int i = blockIdx.x * 1024 + threadIdx.x;
    int v = (i < N) ? deg[i] : 0;
    sm[threadIdx.x] = v;
    __syncthreads();
    for (int o = 1; o < 1024; o <<= 1) {
        int t = (threadIdx.x >= o) ? sm[threadIdx.x - o] : 0;
        __syncthreads();
        sm[threadIdx.x] += t;
        __syncthreads();
    }
    if (i < N) tmp[i] = sm[threadIdx.x];
    if (threadIdx.x == 1023) blks[blockIdx.x] = sm[1023];
}

__global__ void k_scan2(int* blks, int nb) {
    if (threadIdx.x == 0 && blockIdx.x == 0) {
        int run = 0;
        for (int b = 0; b < nb; b++) { int t = blks[b]; blks[b] = run; run += t; }
    }
}

__global__ void k_scan3(const int* __restrict__ tmp, const int* __restrict__ blks,
                        int* __restrict__ rowptr, int N) {
    int i = blockIdx.x * 1024 + threadIdx.x;
    if (i < N) rowptr[i + 1] = tmp[i] + blks[blockIdx.x];
}

__global__ void k_prep(const int* __restrict__ rowptr, const int* __restrict__ deg,
                       int* __restrict__ cursor, float* __restrict__ invdeg, int N) {
    int i = blockIdx.x * blockDim.x + threadIdx.x;
    if (i < N) {
        cursor[i] = rowptr[i];
        int d = deg[i];
        invdeg[i] = 1.0f / (float)max(d, 1);
    }
}

__global__ void k_fill(const int* __restrict__ src, const int* __restrict__ dst,
                       int* __restrict__ cursor, int* __restrict__ srcs, int E) {
    int e = blockIdx.x * blockDim.x + threadIdx.x;
    if (e < E) {
        int p = atomicAdd(&cursor[dst[e]], 1);
        srcs[p] = src[e];
    }
}

// ================= mega kernel: gather + dual-GEMM + bias/relu/LN/resid (+head) ====
// Block = 64 rows x 128 cols, 256 threads.
// SMEM: Hs[64][128] = tile of hin (A for lin_r, residual for layers>0)
//       Ags[64][128] = gathered neighbor means (A for lin_l)
//       Wb[2 stages][8][128][4] = W chunk, layout [i4][n][j] = W[n][k0+4*i4+j]
// Accumulators: ull f32x2 packed over K pairs; final = lo + hi.
// Lane owns cols {lane, 32+lane, 64+lane, 96+lane}; warp wy owns rows wy*8..+7.
__global__ void __launch_bounds__(THREADS, 2)
k_mega(const float* __restrict__ hin,
       const float* __restrict__ W1, const float* __restrict__ W2,
       const float* __restrict__ bias,
       const float* __restrict__ lng, const float* __restrict__ lnb,
       const float* __restrict__ resid_g,   // layer0: g_res; layers 1,2: null -> Hs
       float* __restrict__ outp,
       const int* __restrict__ rowptr, const int* __restrict__ srcs,
       const float* __restrict__ invdeg,
       const float* __restrict__ hw, const float* __restrict__ hb,
       const float* __restrict__ rer, const float* __restrict__ alpha,
       float* __restrict__ score, int M) {
    extern __shared__ float smem[];
    float* Hs  = smem;            // 8192 floats
    float* Ags = smem + 8192;     // 8192 floats
    float* Wb  = smem + 16384;    // 8192 floats (2 x 4096)

    int tid  = threadIdx.x;
    int lane = tid & 31;
    int wy   = tid >> 5;
    int row0 = blockIdx.x * ROWS;
    bool layer = (W2 != nullptr);
    int split   = layer ? 4 : 0;   // chunks < split read Ags, else Hs
    int nchunks = layer ? 8 : 4;

    // ---- issue cp.async for chunk c into stage ----
    auto issue = [&](int c, int stage) {
        const float* W = (c < 4) ? W1 : W2;
        int k0 = (c & 3) * 32;
#pragma unroll
        for (int it = 0; it < 4; it++) {
            int u = tid + it * 256;           // u in [0,1024)
            int i4 = u >> 7, n = u & 127;
            const float* src = W + (size_t)n * D + k0 + i4 * 4;
            unsigned saddr = (unsigned)__cvta_generic_to_shared(Wb + stage * 4096 + u * 4);
            asm volatile("cp.async.ca.shared.global [%0], [%1], 16;" :: "r"(saddr), "l"(src));
        }
        asm volatile("cp.async.commit_group;");
    };

    issue(0, 0);

    // ---- Hs tile: rows row0..row0+63 of hin ----
#pragma unroll
    for (int it = 0; it < 8; it++) {
        int idx = tid + it * 256;             // idx in [0,2048): float4 units
        int row = idx >> 5, c4 = (idx & 31) * 4;
        float4 v = make_float4(0.f, 0.f, 0.f, 0.f);
        int grow = row0 + row;
        if (grow < M) v = *(const float4*)(hin + (size_t)grow * D + c4);
        *(float4*)&Hs[row * D + c4] = v;
    }

    // ---- gather: warp per node, mean of neighbor rows -> Ags ----
    if (srcs) {
        for (int nl = wy; nl < ROWS; nl += 8) {
            int node = row0 + nl;
            if (node >= M) break;             // uniform across warp
            float ax = 0.f, ay = 0.f, az = 0.f, aw = 0.f;
            int e0 = rowptr[node], e1 = rowptr[node + 1];
            for (int e = e0; e < e1; e++) {
                int s = __ldg(&srcs[e]);
                float4 v = *(const float4*)(hin + (size_t)s * D + lane * 4);
                ax += v.x; ay += v.y; az += v.z; aw += v.w;
            }
            float id = invdeg[node];
            *(float4*)&Ags[nl * D + lane * 4] =
                make_float4(ax * id, ay * id, az * id, aw * id);
        }
    }

    ull acc[8][4];
#pragma unroll
    for (int r = 0; r < 8; r++)
#pragma unroll
        for (int c = 0; c < 4; c++) acc[r][c] = 0ull;

    // ---- main k loop over W chunks (32 k each), 2-stage cp.async pipeline ----
    for (int c = 0; c < nchunks; c++) {
        if (c + 1 < nchunks) {
            issue(c + 1, (c + 1) & 1);
            asm volatile("cp.async.wait_group 1;");
        } else {
            asm volatile("cp.async.wait_group 0;");
        }
        __syncthreads();
        const float* Asm = (c < split) ? Ags : Hs;
        const float* Wst = Wb + (c & 1) * 4096;
        int k0 = (c & 3) * 32;
#pragma unroll
        for (int i4 = 0; i4 < 8; i4++) {
            ulonglong2 b0 = *(const ulonglong2*)&Wst[i4 * 512 + (lane)      * 4];
            ulonglong2 b1 = *(const ulonglong2*)&Wst[i4 * 512 + (32 + lane) * 4];
            ulonglong2 b2 = *(const ulonglong2*)&Wst[i4 * 512 + (64 + lane) * 4];
            ulonglong2 b3 = *(const ulonglong2*)&Wst[i4 * 512 + (96 + lane) * 4];
#pragma unroll
            for (int r = 0; r < 8; r++) {
                ulonglong2 a = *(const ulonglong2*)&Asm[(wy * 8 + r) * D + k0 + i4 * 4];
                ffma2(acc[r][0], a.x, b0.x); ffma2(acc[r][0], a.y, b0.y);
                ffma2(acc[r][1], a.x, b1.x); ffma2(acc[r][1], a.y, b1.y);
                ffma2(acc[r][2], a.x, b2.x); ffma2(acc[r][2], a.y, b2.y);
                ffma2(acc[r][3], a.x, b3.x); ffma2(acc[r][3], a.y, b3.y);
            }
        }
        __syncthreads();
    }

    // ---- epilogue ----
    float bz[4], g4[4], lb4[4], w4[4];
    bool doln = (lng != nullptr);
#pragma unroll
    for (int cc = 0; cc < 4; cc++) {
        int col = cc * 32 + lane;
        bz[cc]  = bias ? bias[col] : 0.f;
        g4[cc]  = doln ? lng[col] : 1.f;
        lb4[cc] = doln ? lnb[col] : 0.f;
        w4[cc]  = score ? hw[col] : 0.f;
    }

#pragma unroll
    for (int r = 0; r < 8; r++) {
        int row = row0 + wy * 8 + r;
        if (row >= M) break;                  // uniform across warp
        float v[4];
#pragma unroll
        for (int cc = 0; cc < 4; cc++) {
            float2 f = unpack2(acc[r][cc]);
            v[cc] = f.x + f.y + bz[cc];
        }
        if (doln) {
#pragma unroll
            for (int cc = 0; cc < 4; cc++) v[cc] = fmaxf(v[cc], 0.f);
            float s = v[0] + v[1] + v[2] + v[3];
#pragma unroll
            for (int o = 16; o > 0; o >>= 1) s += __shfl_xor_sync(0xffffffffu, s, o);
            float mu = s * (1.f / 128.f);
            float d0 = v[0] - mu, d1 = v[1] - mu, d2 = v[2] - mu, d3 = v[3] - mu;
            float q = d0 * d0 + d1 * d1 + d2 * d2 + d3 * d3;
#pragma unroll
            for (int o = 16; o > 0; o >>= 1) q += __shfl_xor_sync(0xffffffffu, q, o);
            float rs = rsqrtf(q * (1.f / 128.f) + EPSL);
            v[0] = d0 * rs * g4[0] + lb4[0];
            v[1] = d1 * rs * g4[1] + lb4[1];
            v[2] = d2 * rs * g4[2] + lb4[2];
            v[3] = d3 * rs * g4[3] + lb4[3];
            if (resid_g) {
#pragma unroll
                for (int cc = 0; cc < 4; cc++)
                    v[cc] += resid_g[(size_t)row * D + cc * 32 + lane];
            } else {
                int rl = wy * 8 + r;
#pragma unroll
                for (int cc = 0; cc < 4; cc++)
                    v[cc] += Hs[rl * D + cc * 32 + lane];
            }
        }
        if (score) {
            float sd = v[0] * w4[0] + v[1] * w4[1] + v[2] * w4[2] + v[3] * w4[3];
#pragma unroll
            for (int o = 16; o > 0; o >>= 1) sd += __shfl_xor_sync(0xffffffffu, sd, o);
            if (lane == 0) {
                float gnn = sd + hb[0];
                float a = 1.f / (1.f + expf(-alpha[0]));
                score[row] = a * rer[row] + (1.f - a) * gnn;
            }
        } else {
#pragma unroll
            for (int cc = 0; cc < 4; cc++)
                outp[(size_t)row * D + cc * 32 + lane] = v[cc];
        }
    }
}

// ---------------- launch ----------------
extern "C" void kernel_launch(void* const* d_in, const int* in_sizes, int n_in,
                              void* d_out, int out_size) {
    const float* x       = (const float*)d_in[0];
    const int*   ei      = (const int*)  d_in[1];
    const float* rer     = (const float*)d_in[2];
    const float* proj_w  = (const float*)d_in[3];
    const float* proj_b  = (const float*)d_in[4];
    const float* lin_l_w = (const float*)d_in[5];
    const float* lin_l_b = (const float*)d_in[6];
    const float* lin_r_w = (const float*)d_in[7];
    const float* ln_g    = (const float*)d_in[8];
    const float* ln_b    = (const float*)d_in[9];
    const float* head_w  = (const float*)d_in[10];
    const float* head_b  = (const float*)d_in[11];
    const float* alpha   = (const float*)d_in[12];

    int N = in_sizes[0] / D;
    int E = in_sizes[1] / 2;
    const int* src = ei;
    const int* dst = ei + E;
    float* out = (float*)d_out;

    float *res, *h0, *h1, *invdeg;
    int *deg, *rowptr, *cursor, *stmp, *blks, *srcs;
    cudaGetSymbolAddress((void**)&res,    g_res);
    cudaGetSymbolAddress((void**)&h0,     g_h0);
    cudaGetSymbolAddress((void**)&h1,     g_h1);
    cudaGetSymbolAddress((void**)&invdeg, g_invdeg);
    cudaGetSymbolAddress((void**)&deg,    g_deg);
    cudaGetSymbolAddress((void**)&rowptr, g_rowptr);
    cudaGetSymbolAddress((void**)&cursor, g_cursor);
    cudaGetSymbolAddress((void**)&stmp,   g_scantmp);
    cudaGetSymbolAddress((void**)&blks,   g_blksums);
    cudaGetSymbolAddress((void**)&srcs,   g_srcsorted);

    int nb = (N + 1023) / 1024;

    // CSR build
    k_zero <<<(N + 255) / 256, 256>>>(deg, rowptr, N);
    k_count<<<(E + 255) / 256, 256>>>(dst, deg, E);
    k_scan1<<<nb, 1024>>>(deg, stmp, blks, N);
    k_scan2<<<1, 32>>>(blks, nb);
    k_scan3<<<nb, 1024>>>(stmp, blks, rowptr, N);
    k_prep <<<(N + 255) / 256, 256>>>(rowptr, deg, cursor, invdeg, N);
    k_fill <<<(E + 255) / 256, 256>>>(src, dst, cursor, srcs, E);

    const int SMEM = 24576 * sizeof(float);  // 96 KB
    cudaFuncSetAttribute(k_mega, cudaFuncAttributeMaxDynamicSharedMemorySize, SMEM);

    int blocks = (N + ROWS - 1) / ROWS;

    // residual = x @ proj_w^T + proj_b   (no gather, no LN)
    k_mega<<<blocks, THREADS, SMEM>>>(x, proj_w, nullptr, proj_b,
                                      nullptr, nullptr, nullptr, res,
                                      nullptr, nullptr, nullptr,
                                      nullptr, nullptr, nullptr, nullptr, nullptr, N);

    const float* h_cur = x;
    float* bufs[2] = {h0, h1};
    for (int i = 0; i < 3; i++) {
        float* h_next = bufs[i & 1];
        bool last = (i == 2);
        k_mega<<<blocks, THREADS, SMEM>>>(h_cur,
                                          lin_l_w + (size_t)i * D * D,
                                          lin_r_w + (size_t)i * D * D,
                                          lin_l_b + (size_t)i * D,
                                          ln_g + (size_t)i * D, ln_b + (size_t)i * D,
                                          (i == 0) ? res : nullptr,
                                          last ? nullptr : h_next,
                                          rowptr, srcs, invdeg,
                                          last ? head_w : nullptr,
                                          last ? head_b : nullptr,
                                          last ? rer    : nullptr,
                                          last ? alpha  : nullptr,
                                          last ? out    : nullptr, N);
        h_cur = h_next;
    }
}

// round 4
// speedup vs baseline: 1.0955x; 1.0955x over previous
#include <cuda_runtime.h>
#include <math.h>

#define D 128
#define MAXN 100096
#define MAXE 1600256
#define EPSL 1e-5f
#define ROWS 64
#define THREADS 256

typedef unsigned long long ull;

__device__ __forceinline__ void ffma2(ull &d, ull a, ull b) {
    asm("fma.rn.f32x2 %0, %1, %2, %0;" : "+l"(d) : "l"(a), "l"(b));
}
__device__ __forceinline__ float2 unpack2(ull v) {
    float2 f; asm("mov.b64 {%0, %1}, %2;" : "=f"(f.x), "=f"(f.y) : "l"(v)); return f;
}

// ---------------- scratch (device globals: no allocation allowed) ----------------
__device__ float g_res[(size_t)MAXN * D];
__device__ float g_agg[(size_t)MAXN * D];
__device__ float g_h0 [(size_t)MAXN * D];
__device__ float g_h1 [(size_t)MAXN * D];
__device__ float g_invdeg[MAXN];
__device__ int   g_deg[MAXN];
__device__ int   g_rowptr[MAXN + 1];
__device__ int   g_cursor[MAXN];
__device__ int   g_scantmp[MAXN];
__device__ int   g_blksums[256];
__device__ int   g_srcsorted[MAXE];

// ---------------- CSR build ----------------
__global__ void k_zero(int* deg, int* rowptr, int N) {
    int i = blockIdx.x * blockDim.x + threadIdx.x;
    if (i < N) deg[i] = 0;
    if (i == 0) rowptr[0] = 0;
}

__global__ void k_count(const int* __restrict__ dst, int* __restrict__ deg, int E) {
    int e = blockIdx.x * blockDim.x + threadIdx.x;
    if (e < E) atomicAdd(&deg[dst[e]], 1);
}

__global__ void k_scan1(const int* __restrict__ deg, int* __restrict__ tmp,
                        int* __restrict__ blks, int N) {
    __shared__ int sm[1024];
    int i = blockIdx.x * 1024 + threadIdx.x;
    int v = (i < N) ? deg[i] : 0;
    sm[threadIdx.x] = v;
    __syncthreads();
    for (int o = 1; o < 1024; o <<= 1) {
        int t = (threadIdx.x >= o) ? sm[threadIdx.x - o] : 0;
        __syncthreads();
        sm[threadIdx.x] += t;
        __syncthreads();
    }
    if (i < N) tmp[i] = sm[threadIdx.x];
    if (threadIdx.x == 1023) blks[blockIdx.x] = sm[1023];
}

__global__ void k_scan2(int* blks, int nb) {
    if (threadIdx.x == 0 && blockIdx.x == 0) {
        int run = 0;
        for (int b = 0; b < nb; b++) { int t = blks[b]; blks[b] = run; run += t; }
    }
}

__global__ void k_scan3(const int* __restrict__ tmp, const int* __restrict__ blks,
                        int* __restrict__ rowptr, int N) {
    int i = blockIdx.x * 1024 + threadIdx.x;
    if (i < N) rowptr[i + 1] = tmp[i] + blks[blockIdx.x];
}

__global__ void k_prep(const int* __restrict__ rowptr, const int* __restrict__ deg,
                       int* __restrict__ cursor, float* __restrict__ invdeg, int N) {
    int i = blockIdx.x * blockDim.x + threadIdx.x;
    if (i < N) {
        cursor[i] = rowptr[i];
        int d = deg[i];
        invdeg[i] = 1.0f / (float)max(d, 1);
    }
}

__global__ void k_fill(const int* __restrict__ src, const int* __restrict__ dst,
                       int* __restrict__ cursor, int* __restrict__ srcs, int E) {
    int e = blockIdx.x * blockDim.x + threadIdx.x;
    if (e < E) {
        int p = atomicAdd(&cursor[dst[e]], 1);
        srcs[p] = src[e];
    }
}

// ---------------- mean aggregation: warp per node, float4 lanes ----------------
__global__ void k_aggregate(const float* __restrict__ h, const int* __restrict__ rowptr,
                            const int* __restrict__ srcs, const float* __restrict__ invdeg,
                            float* __restrict__ agg, int N) {
    int node = blockIdx.x * (blockDim.x >> 5) + (threadIdx.x >> 5);
    if (node >= N) return;
    int lane = threadIdx.x & 31;
    float ax = 0.f, ay = 0.f, az = 0.f, aw = 0.f;
    int e0 = rowptr[node], e1 = rowptr[node + 1];
    for (int e = e0; e < e1; e++) {
        int s = __ldg(&srcs[e]);
        float4 v = *(const float4*)(h + (size_t)s * D + lane * 4);
        ax += v.x; ay += v.y; az += v.z; aw += v.w;
    }
    float id = invdeg[node];
    *(float4*)(agg + (size_t)node * D + lane * 4) = make_float4(ax * id, ay * id, az * id, aw * id);
}

// ============ dual-GEMM + bias/relu/LN/resid (+head), K-pair f32x2 packing ========
// Block = 64 rows x 128 cols, 256 threads. Lane owns cols {lane,32+lane,64+lane,96+lane};
// warp wy owns rows wy*8..+7.
// SMEM: As[2][64][128] row-major A tiles (A1, A2) -> a-operand is broadcast LDS.128
//       Wb[2 stages][8][128][4]: Wb[i4][n][j] = W[n][k0+4*i4+j] (written by cp.async)
// acc packed f32x2 over adjacent K; final = lo+hi. Zero pack movs in inner loop.
__global__ void __launch_bounds__(THREADS, 2)
k_gemm2(const float* __restrict__ A1, const float* __restrict__ W1,
        const float* __restrict__ A2, const float* __restrict__ W2,
        const float* __restrict__ bias,
        const float* __restrict__ lng, const float* __restrict__ lnb,
        const float* __restrict__ resid,
        float* __restrict__ outp,
        const float* __restrict__ hw, const float* __restrict__ hb,
        const float* __restrict__ rer, const float* __restrict__ alpha,
        float* __restrict__ score, int M) {
    extern __shared__ float smem[];
    float* As = smem;             // 2 x 8192 floats
    float* Wb = smem + 16384;     // 2 x 4096 floats

    int tid  = threadIdx.x;
    int lane = tid & 31;
    int wy   = tid >> 5;
    int row0 = blockIdx.x * ROWS;
    int nchunks = (A2 != nullptr) ? 8 : 4;

    auto issue = [&](int c, int stage) {
        const float* W = (c < 4) ? W1 : W2;
        int k0 = (c & 3) * 32;
#pragma unroll
        for (int it = 0; it < 4; it++) {
            int u = tid + it * 256;           // u in [0,1024)
            int i4 = u >> 7, n = u & 127;
            const float* src = W + (size_t)n * D + k0 + i4 * 4;
            unsigned saddr = (unsigned)__cvta_generic_to_shared(Wb + stage * 4096 + u * 4);
            asm volatile("cp.async.ca.shared.global [%0], [%1], 16;" :: "r"(saddr), "l"(src));
        }
        asm volatile("cp.async.commit_group;");
    };

    issue(0, 0);
    issue(1, 1);

    // ---- A tiles (row-major) ----
#pragma unroll
    for (int it = 0; it < 8; it++) {
        int idx = tid + it * 256;             // float4 units, [0,2048)
        int row = idx >> 5, c4 = (idx & 31) * 4;
        int grow = row0 + row;
        float4 v = make_float4(0.f, 0.f, 0.f, 0.f);
        if (grow < M) v = *(const float4*)(A1 + (size_t)grow * D + c4);
        *(float4*)&As[row * D + c4] = v;
    }
    if (A2) {
#pragma unroll
        for (int it = 0; it < 8; it++) {
            int idx = tid + it * 256;
            int row = idx >> 5, c4 = (idx & 31) * 4;
            int grow = row0 + row;
            float4 v = make_float4(0.f, 0.f, 0.f, 0.f);
            if (grow < M) v = *(const float4*)(A2 + (size_t)grow * D + c4);
            *(float4*)&As[8192 + row * D + c4] = v;
        }
    }

    ull acc[8][4];
#pragma unroll
    for (int r = 0; r < 8; r++)
#pragma unroll
        for (int c = 0; c < 4; c++) acc[r][c] = 0ull;

    // ---- main loop: 32-k chunks, 2-stage cp.async pipeline ----
    for (int c = 0; c < nchunks; c++) {
        if (c + 2 < nchunks) {
            asm volatile("cp.async.wait_group 1;");
        } else {
            asm volatile("cp.async.wait_group 0;");
        }
        __syncthreads();
        const float* Asm = As + ((c < 4) ? 0 : 8192);
        const float* Wst = Wb + (c & 1) * 4096;
        int k0 = (c & 3) * 32;
#pragma unroll
        for (int i4 = 0; i4 < 8; i4++) {
            ulonglong2 b0 = *(const ulonglong2*)&Wst[i4 * 512 + (lane)      * 4];
            ulonglong2 b1 = *(const ulonglong2*)&Wst[i4 * 512 + (32 + lane) * 4];
            ulonglong2 b2 = *(const ulonglong2*)&Wst[i4 * 512 + (64 + lane) * 4];
            ulonglong2 b3 = *(const ulonglong2*)&Wst[i4 * 512 + (96 + lane) * 4];
#pragma unroll
            for (int r = 0; r < 8; r++) {
                ulonglong2 a = *(const ulonglong2*)&Asm[(wy * 8 + r) * D + k0 + i4 * 4];
                ffma2(acc[r][0], a.x, b0.x); ffma2(acc[r][0], a.y, b0.y);
                ffma2(acc[r][1], a.x, b1.x); ffma2(acc[r][1], a.y, b1.y);
                ffma2(acc[r][2], a.x, b2.x); ffma2(acc[r][2], a.y, b2.y);
                ffma2(acc[r][3], a.x, b3.x); ffma2(acc[r][3], a.y, b3.y);
            }
        }
        __syncthreads();
        if (c + 2 < nchunks) issue(c + 2, c & 1);
    }

    // ---- epilogue ----
    float bz[4], g4[4], lb4[4], w4[4];
    bool doln = (lng != nullptr);
#pragma unroll
    for (int cc = 0; cc < 4; cc++) {
        int col = cc * 32 + lane;
        bz[cc]  = bias ? bias[col] : 0.f;
        g4[cc]  = doln ? lng[col] : 1.f;
        lb4[cc] = doln ? lnb[col] : 0.f;
        w4[cc]  = score ? hw[col] : 0.f;
    }

#pragma unroll
    for (int r = 0; r < 8; r++) {
        int row = row0 + wy * 8 + r;
        if (row >= M) break;                  // uniform across warp
        float v[4];
#pragma unroll
        for (int cc = 0; cc < 4; cc++) {
            float2 f = unpack2(acc[r][cc]);
            v[cc] = f.x + f.y + bz[cc];
        }
        if (doln) {
#pragma unroll
            for (int cc = 0; cc < 4; cc++) v[cc] = fmaxf(v[cc], 0.f);
            float s = v[0] + v[1] + v[2] + v[3];
#pragma unroll
            for (int o = 16; o > 0; o >>= 1) s += __shfl_xor_sync(0xffffffffu, s, o);
            float mu = s * (1.f / 128.f);
            float d0 = v[0] - mu, d1 = v[1] - mu, d2 = v[2] - mu, d3 = v[3] - mu;
            float q = d0 * d0 + d1 * d1 + d2 * d2 + d3 * d3;
#pragma unroll
            for (int o = 16; o > 0; o >>= 1) q += __shfl_xor_sync(0xffffffffu, q, o);
            float rs = rsqrtf(q * (1.f / 128.f) + EPSL);
            v[0] = d0 * rs * g4[0] + lb4[0];
            v[1] = d1 * rs * g4[1] + lb4[1];
            v[2] = d2 * rs * g4[2] + lb4[2];
            v[3] = d3 * rs * g4[3] + lb4[3];
#pragma unroll
            for (int cc = 0; cc < 4; cc++)
                v[cc] += resid[(size_t)row * D + cc * 32 + lane];
        }
        if (score) {
            float sd = v[0] * w4[0] + v[1] * w4[1] + v[2] * w4[2] + v[3] * w4[3];
#pragma unroll
            for (int o = 16; o > 0; o >>= 1) sd += __shfl_xor_sync(0xffffffffu, sd, o);
            if (lane == 0) {
                float gnn = sd + hb[0];
                float a = 1.f / (1.f + expf(-alpha[0]));
                score[row] = a * rer[row] + (1.f - a) * gnn;
            }
        } else {
#pragma unroll
            for (int cc = 0; cc < 4; cc++)
                outp[(size_t)row * D + cc * 32 + lane] = v[cc];
        }
    }
}

// ---------------- launch ----------------
extern "C" void kernel_launch(void* const* d_in, const int* in_sizes, int n_in,
                              void* d_out, int out_size) {
    const float* x       = (const float*)d_in[0];
    const int*   ei      = (const int*)  d_in[1];
    const float* rer     = (const float*)d_in[2];
    const float* proj_w  = (const float*)d_in[3];
    const float* proj_b  = (const float*)d_in[4];
    const float* lin_l_w = (const float*)d_in[5];
    const float* lin_l_b = (const float*)d_in[6];
    const float* lin_r_w = (const float*)d_in[7];
    const float* ln_g    = (const float*)d_in[8];
    const float* ln_b    = (const float*)d_in[9];
    const float* head_w  = (const float*)d_in[10];
    const float* head_b  = (const float*)d_in[11];
    const float* alpha   = (const float*)d_in[12];

    int N = in_sizes[0] / D;
    int E = in_sizes[1] / 2;
    const int* src = ei;
    const int* dst = ei + E;
    float* out = (float*)d_out;

    float *res, *agg, *h0, *h1, *invdeg;
    int *deg, *rowptr, *cursor, *stmp, *blks, *srcs;
    cudaGetSymbolAddress((void**)&res,    g_res);
    cudaGetSymbolAddress((void**)&agg,    g_agg);
    cudaGetSymbolAddress((void**)&h0,     g_h0);
    cudaGetSymbolAddress((void**)&h1,     g_h1);
    cudaGetSymbolAddress((void**)&invdeg, g_invdeg);
    cudaGetSymbolAddress((void**)&deg,    g_deg);
    cudaGetSymbolAddress((void**)&rowptr, g_rowptr);
    cudaGetSymbolAddress((void**)&cursor, g_cursor);
    cudaGetSymbolAddress((void**)&stmp,   g_scantmp);
    cudaGetSymbolAddress((void**)&blks,   g_blksums);
    cudaGetSymbolAddress((void**)&srcs,   g_srcsorted);

    int nb = (N + 1023) / 1024;

    // CSR build
    k_zero <<<(N + 255) / 256, 256>>>(deg, rowptr, N);
    k_count<<<(E + 255) / 256, 256>>>(dst, deg, E);
    k_scan1<<<nb, 1024>>>(deg, stmp, blks, N);
    k_scan2<<<1, 32>>>(blks, nb);
    k_scan3<<<nb, 1024>>>(stmp, blks, rowptr, N);
    k_prep <<<(N + 255) / 256, 256>>>(rowptr, deg, cursor, invdeg, N);
    k_fill <<<(E + 255) / 256, 256>>>(src, dst, cursor, srcs, E);

    const int SMEM = 24576 * sizeof(float);  // 96 KB
    cudaFuncSetAttribute(k_gemm2, cudaFuncAttributeMaxDynamicSharedMemorySize, SMEM);

    int blocks = (N + ROWS - 1) / ROWS;
    int warp_blocks = (N + 7) / 8;

    // residual = x @ proj_w^T + proj_b
    k_gemm2<<<blocks, THREADS, SMEM>>>(x, proj_w, nullptr, nullptr, proj_b,
                                       nullptr, nullptr, nullptr, res,
                                       nullptr, nullptr, nullptr, nullptr, nullptr, N);

    const float* h_cur = x;
    float* bufs[2] = {h0, h1};
    for (int i = 0; i < 3; i++) {
        float* h_next = bufs[i & 1];
        bool last = (i == 2);
        k_aggregate<<<warp_blocks, 256>>>(h_cur, rowptr, srcs, invdeg, agg, N);
        k_gemm2<<<blocks, THREADS, SMEM>>>(agg, lin_l_w + (size_t)i * D * D,
                                           h_cur, lin_r_w + (size_t)i * D * D,
                                           lin_l_b + (size_t)i * D,
                                           ln_g + (size_t)i * D, ln_b + (size_t)i * D,
                                           (i == 0) ? res : h_cur,
                                           last ? nullptr : h_next,
                                           last ? head_w : nullptr,
                                           last ? head_b : nullptr,
                                           last ? rer    : nullptr,
                                           last ? alpha  : nullptr,
                                           last ? out    : nullptr, N);
        h_cur = h_next;
    }
}

// round 6
// speedup vs baseline: 1.5853x; 1.4471x over previous
#include <cuda_runtime.h>
#include <cuda_bf16.h>
#include <math.h>
#include <cstdint>

#define D 128
#define MAXN 100096
#define MAXE 1600256
#define EPSL 1e-5f
#define TILE_M 128
#define THREADS 256
// bf16 tile row stride (elements): 128 + 8 pad -> 272B rows, conflict-free ldmatrix
#define TSTR 136

// ---------------- scratch ----------------
__device__ float g_res[(size_t)MAXN * D];
__device__ float g_agg[(size_t)MAXN * D];
__device__ float g_h0 [(size_t)MAXN * D];
__device__ float g_h1 [(size_t)MAXN * D];
__device__ float g_invdeg[MAXN];
__device__ int   g_deg[MAXN];
__device__ int   g_rowptr[MAXN + 1];
__device__ int   g_cursor[MAXN];
__device__ int   g_scantmp[MAXN];
__device__ int   g_blksums[256];
__device__ int   g_srcsorted[MAXE];
__device__ __nv_bfloat16 g_whi[7 * 128 * 128];
__device__ __nv_bfloat16 g_wlo[7 * 128 * 128];

// ---------------- CSR build ----------------
__global__ void k_zero(int* deg, int* rowptr, int N) {
    int i = blockIdx.x * blockDim.x + threadIdx.x;
    if (i < N) deg[i] = 0;
    if (i == 0) rowptr[0] = 0;
}
__global__ void k_count(const int* __restrict__ dst, int* __restrict__ deg, int E) {
    int e = blockIdx.x * blockDim.x + threadIdx.x;
    if (e < E) atomicAdd(&deg[dst[e]], 1);
}
__global__ void k_scan1(const int* __restrict__ deg, int* __restrict__ tmp,
                        int* __restrict__ blks, int N) {
    __shared__ int sm[1024];
    int i = blockIdx.x * 1024 + threadIdx.x;
    int v = (i < N) ? deg[i] : 0;
    sm[threadIdx.x] = v;
    __syncthreads();
    for (int o = 1; o < 1024; o <<= 1) {
        int t = (threadIdx.x >= o) ? sm[threadIdx.x - o] : 0;
        __syncthreads();
        sm[threadIdx.x] += t;
        __syncthreads();
    }
    if (i < N) tmp[i] = sm[threadIdx.x];
    if (threadIdx.x == 1023) blks[blockIdx.x] = sm[1023];
}
__global__ void k_scan2(int* blks, int nb) {
    if (threadIdx.x == 0 && blockIdx.x == 0) {
        int run = 0;
        for (int b = 0; b < nb; b++) { int t = blks[b]; blks[b] = run; run += t; }
    }
}
__global__ void k_scan3(const int* __restrict__ tmp, const int* __restrict__ blks,
                        int* __restrict__ rowptr, int N) {
    int i = blockIdx.x * 1024 + threadIdx.x;
    if (i < N) rowptr[i + 1] = tmp[i] + blks[blockIdx.x];
}
__global__ void k_prep(const int* __restrict__ rowptr, const int* __restrict__ deg,
                       int* __restrict__ cursor, float* __restrict__ invdeg, int N) {
    int i = blockIdx.x * blockDim.x + threadIdx.x;
    if (i < N) {
        cursor[i] = rowptr[i];
        invdeg[i] = 1.0f / (float)max(deg[i], 1);
    }
}
__global__ void k_fill(const int* __restrict__ src, const int* __restrict__ dst,
                       int* __restrict__ cursor, int* __restrict__ srcs, int E) {
    int e = blockIdx.x * blockDim.x + threadIdx.x;
    if (e < E) {
        int p = atomicAdd(&cursor[dst[e]], 1);
        srcs[p] = src[e];
    }
}

// ---------------- weight split fp32 -> bf16 hi/lo ----------------
__global__ void k_wsplit(const float* __restrict__ proj_w, const float* __restrict__ lin_l_w,
                         const float* __restrict__ lin_r_w,
                         __nv_bfloat16* __restrict__ whi, __nv_bfloat16* __restrict__ wlo) {
    int i = blockIdx.x * blockDim.x + threadIdx.x;
    if (i >= 7 * 16384) return;
    int m = i >> 14, e = i & 16383;
    float v = (m == 0) ? proj_w[e] : (m <= 3 ? lin_l_w[(m - 1) * 16384 + e]
                                             : lin_r_w[(m - 4) * 16384 + e]);
    __nv_bfloat16 h = __float2bfloat16(v);
    whi[i] = h;
    wlo[i] = __float2bfloat16(v - __bfloat162float(h));
}

// ---------------- mean aggregation: warp per node ----------------
__global__ void k_aggregate(const float* __restrict__ h, const int* __restrict__ rowptr,
                            const int* __restrict__ srcs, const float* __restrict__ invdeg,
                            float* __restrict__ agg, int N) {
    int node = blockIdx.x * (blockDim.x >> 5) + (threadIdx.x >> 5);
    if (node >= N) return;
    int lane = threadIdx.x & 31;
    float ax = 0.f, ay = 0.f, az = 0.f, aw = 0.f;
    int e0 = rowptr[node], e1 = rowptr[node + 1];
    for (int e = e0; e < e1; e++) {
        int s = __ldg(&srcs[e]);
        float4 v = *(const float4*)(h + (size_t)s * D + lane * 4);
        ax += v.x; ay += v.y; az += v.z; aw += v.w;
    }
    float id = invdeg[node];
    *(float4*)(agg + (size_t)node * D + lane * 4) = make_float4(ax * id, ay * id, az * id, aw * id);
}

// ---------------- mma.sync helpers ----------------
__device__ __forceinline__ void ldsm4(uint32_t* r, uint32_t saddr) {
    asm volatile("ldmatrix.sync.aligned.m8n8.x4.shared.b16 {%0,%1,%2,%3}, [%4];"
                 : "=r"(r[0]), "=r"(r[1]), "=r"(r[2]), "=r"(r[3]) : "r"(saddr));
}
__device__ __forceinline__ void mma_bf16(float* c, const uint32_t* a, uint32_t b0, uint32_t b1) {
    asm volatile(
        "mma.sync.aligned.m16n8k16.row.col.f32.bf16.bf16.f32 "
        "{%0,%1,%2,%3}, {%4,%5,%6,%7}, {%8,%9}, {%0,%1,%2,%3};"
        : "+f"(c[0]), "+f"(c[1]), "+f"(c[2]), "+f"(c[3])
        : "r"(a[0]), "r"(a[1]), "r"(a[2]), "r"(a[3]), "r"(b0), "r"(b1));
}

// =================== HMMA dual-GEMM + bias/relu/LN/resid (+head) ===================
// Block = 128x128 tile, 256 threads, warp grid 2(M) x 4(N); warp tile 64x32.
// Split GEMM: D = Ahi*Whi + Ahi*Wlo + Alo*Whi (fp32 acc).
// SMEM tiles bf16 [128][TSTR]: Ahi, Alo, Bhi, Blo. Epilogue stages acc in fp32 Sg[128][132]
// (overlaps tile space), then per-row LN/resid/head like the SIMT version.
#define OFF_AHI 0
#define OFF_ALO (128 * TSTR * 2)
#define OFF_BHI (2 * 128 * TSTR * 2)
#define OFF_BLO (3 * 128 * TSTR * 2)
#define OFF_PAR (4 * 128 * TSTR * 2)          // bias/lng/lnb/hw: 4 x 512B
#define SMEM_BYTES (OFF_PAR + 4 * 512)

__global__ void __launch_bounds__(THREADS, 1)
k_tcgemm(const float* __restrict__ A1, const float* __restrict__ A2,
         const __nv_bfloat16* __restrict__ Whi1, const __nv_bfloat16* __restrict__ Wlo1,
         const __nv_bfloat16* __restrict__ Whi2, const __nv_bfloat16* __restrict__ Wlo2,
         const float* __restrict__ bias,
         const float* __restrict__ lng, const float* __restrict__ lnb,
         const float* __restrict__ resid,
         float* __restrict__ outp,
         const float* __restrict__ hw, const float* __restrict__ hb,
         const float* __restrict__ rer, const float* __restrict__ alpha,
         float* __restrict__ score, int M) {
    extern __shared__ __align__(16) char sg[];
    uint32_t sb = (uint32_t)__cvta_generic_to_shared(sg);

    int tid  = threadIdx.x;
    int lane = tid & 31;
    int wid  = tid >> 5;
    int wm   = wid >> 2;          // 0..1  -> m offset wm*64
    int wn   = wid & 3;           // 0..3  -> n offset wn*32
    int row0 = blockIdx.x * TILE_M;

    float* bias_s = (float*)(sg + OFF_PAR);
    float* lng_s  = (float*)(sg + OFF_PAR + 512);
    float* lnb_s  = (float*)(sg + OFF_PAR + 1024);
    float* hw_s   = (float*)(sg + OFF_PAR + 1536);
    float* Sg     = (float*)sg;   // epilogue staging 128 x 132 fp32 (overlaps tiles)

    if (tid < 128) {
        bias_s[tid] = bias ? bias[tid] : 0.f;
        lng_s[tid]  = lng ? lng[tid] : 1.f;
        lnb_s[tid]  = lnb ? lnb[tid] : 0.f;
        hw_s[tid]   = hw  ? hw[tid]  : 0.f;
    }

    float acc[4][4][4];           // [m-tile][n-tile][c0..c3]
#pragma unroll
    for (int mt = 0; mt < 4; mt++)
#pragma unroll
        for (int nt = 0; nt < 4; nt++)
#pragma unroll
            for (int c = 0; c < 4; c++) acc[mt][nt][c] = 0.f;

    // ldmatrix per-lane address pieces (x4 over 16 rows, 2 k-halves)
    int frow = lane & 15;         // row within 16-row ldmatrix footprint
    int fcol = (lane >> 4) * 8;   // k offset 0 or 8

    for (int pass = 0; pass < 2; pass++) {
        const float* A = pass ? A2 : A1;
        if (A == nullptr) break;
        const __nv_bfloat16* Whi = pass ? Whi2 : Whi1;
        const __nv_bfloat16* Wlo = pass ? Wlo2 : Wlo1;

        // W tiles via cp.async (bf16 source), padded rows
#pragma unroll
        for (int it = 0; it < 8; it++) {
            int u = tid + it * 256;           // 0..2047 : 128 rows x 16 chunks
            int n = u >> 4, c16 = u & 15;
            uint32_t doff = (uint32_t)(n * TSTR * 2 + c16 * 16);
            asm volatile("cp.async.ca.shared.global [%0], [%1], 16;"
                         :: "r"(sb + OFF_BHI + doff), "l"(Whi + n * 128 + c16 * 8));
            asm volatile("cp.async.ca.shared.global [%0], [%1], 16;"
                         :: "r"(sb + OFF_BLO + doff), "l"(Wlo + n * 128 + c16 * 8));
        }
        asm volatile("cp.async.commit_group;");

        // A tile: fp32 load, split to bf16 hi/lo, padded rows
#pragma unroll
        for (int it = 0; it < 16; it++) {
            int idx = tid + it * 256;         // 0..4095 float4 units
            int r = idx >> 5, k0 = (idx & 31) * 4;
            float4 v = make_float4(0.f, 0.f, 0.f, 0.f);
            int grow = row0 + r;
            if (grow < M) v = *(const float4*)(A + (size_t)grow * D + k0);
            __nv_bfloat16 h0 = __float2bfloat16(v.x), h1 = __float2bfloat16(v.y);
            __nv_bfloat16 h2 = __float2bfloat16(v.z), h3 = __float2bfloat16(v.w);
            __nv_bfloat16 l0 = __float2bfloat16(v.x - __bfloat162float(h0));
            __nv_bfloat16 l1 = __float2bfloat16(v.y - __bfloat162float(h1));
            __nv_bfloat16 l2 = __float2bfloat16(v.z - __bfloat162float(h2));
            __nv_bfloat16 l3 = __float2bfloat16(v.w - __bfloat162float(h3));
            uint32_t hi01 = ((uint32_t)__bfloat16_as_ushort(h1) << 16) | __bfloat16_as_ushort(h0);
            uint32_t hi23 = ((uint32_t)__bfloat16_as_ushort(h3) << 16) | __bfloat16_as_ushort(h2);
            uint32_t lo01 = ((uint32_t)__bfloat16_as_ushort(l1) << 16) | __bfloat16_as_ushort(l0);
            uint32_t lo23 = ((uint32_t)__bfloat16_as_ushort(l3) << 16) | __bfloat16_as_ushort(l2);
            int doff = r * TSTR * 2 + k0 * 2;
            *(uint2*)(sg + OFF_AHI + doff) = make_uint2(hi01, hi23);
            *(uint2*)(sg + OFF_ALO + doff) = make_uint2(lo01, lo23);
        }

        asm volatile("cp.async.wait_group 0;");
        __syncthreads();

        uint32_t aoff = (uint32_t)(((wm * 64 + frow) * TSTR + fcol) * 2);
        uint32_t boff = (uint32_t)(((wn * 32 + frow) * TSTR + fcol) * 2);

#pragma unroll
        for (int ks = 0; ks < 8; ks++) {
            uint32_t kb = (uint32_t)(ks * 32);   // 16 bf16 = 32 B
            uint32_t ah[4][4], al[4][4], bh[2][4], bl[2][4];
#pragma unroll
            for (int mt = 0; mt < 4; mt++) {
                ldsm4(ah[mt], sb + OFF_AHI + aoff + mt * 16 * TSTR * 2 + kb);
                ldsm4(al[mt], sb + OFF_ALO + aoff + mt * 16 * TSTR * 2 + kb);
            }
#pragma unroll
            for (int p = 0; p < 2; p++) {
                ldsm4(bh[p], sb + OFF_BHI + boff + p * 16 * TSTR * 2 + kb);
                ldsm4(bl[p], sb + OFF_BLO + boff + p * 16 * TSTR * 2 + kb);
            }
#pragma unroll
            for (int mt = 0; mt < 4; mt++) {
#pragma unroll
                for (int nt = 0; nt < 4; nt++) {
                    int p = nt >> 1, q = nt & 1;
                    mma_bf16(acc[mt][nt], ah[mt], bh[p][q], bh[p][q + 2]);  // hi*hi
                    mma_bf16(acc[mt][nt], ah[mt], bl[p][q], bl[p][q + 2]);  // hi*lo
                    mma_bf16(acc[mt][nt], al[mt], bh[p][q], bh[p][q + 2]);  // lo*hi
                }
            }
        }
        __syncthreads();
    }

    // ---- stage accumulators to SMEM (fp32, row stride 132) ----
#pragma unroll
    for (int mt = 0; mt < 4; mt++) {
#pragma unroll
        for (int nt = 0; nt < 4; nt++) {
            int m = wm * 64 + mt * 16 + (lane >> 2);
            int n = wn * 32 + nt * 8 + (lane & 3) * 2;
            *(float2*)&Sg[m * 132 + n]       = make_float2(acc[mt][nt][0], acc[mt][nt][1]);
            *(float2*)&Sg[(m + 8) * 132 + n] = make_float2(acc[mt][nt][2], acc[mt][nt][3]);
        }
    }
    __syncthreads();

    // ---- per-row epilogue: bias (+relu+LN+resid) (+head) ----
    bool doln = (lng != nullptr);
#pragma unroll
    for (int rr = 0; rr < 16; rr++) {
        int row_l = wid * 16 + rr;
        int grow = row0 + row_l;
        if (grow >= M) break;                 // uniform across warp
        float v[4];
#pragma unroll
        for (int cc = 0; cc < 4; cc++)
            v[cc] = Sg[row_l * 132 + cc * 32 + lane] + bias_s[cc * 32 + lane];
        if (doln) {
#pragma unroll
            for (int cc = 0; cc < 4; cc++) v[cc] = fmaxf(v[cc], 0.f);
            float s = v[0] + v[1] + v[2] + v[3];
#pragma unroll
            for (int o = 16; o > 0; o >>= 1) s += __shfl_xor_sync(0xffffffffu, s, o);
            float mu = s * (1.f / 128.f);
            float d0 = v[0] - mu, d1 = v[1] - mu, d2 = v[2] - mu, d3 = v[3] - mu;
            float q = d0 * d0 + d1 * d1 + d2 * d2 + d3 * d3;
#pragma unroll
            for (int o = 16; o > 0; o >>= 1) q += __shfl_xor_sync(0xffffffffu, q, o);
            float rs = rsqrtf(q * (1.f / 128.f) + EPSL);
            v[0] = d0 * rs * lng_s[lane]       + lnb_s[lane];
            v[1] = d1 * rs * lng_s[32 + lane]  + lnb_s[32 + lane];
            v[2] = d2 * rs * lng_s[64 + lane]  + lnb_s[64 + lane];
            v[3] = d3 * rs * lng_s[96 + lane]  + lnb_s[96 + lane];
#pragma unroll
            for (int cc = 0; cc < 4; cc++)
                v[cc] += resid[(size_t)grow * D + cc * 32 + lane];
        }
        if (score) {
            float sd = v[0] * hw_s[lane] + v[1] * hw_s[32 + lane]
                     + v[2] * hw_s[64 + lane] + v[3] * hw_s[96 + lane];
#pragma unroll
            for (int o = 16; o > 0; o >>= 1) sd += __shfl_xor_sync(0xffffffffu, sd, o);
            if (lane == 0) {
                float gnn = sd + hb[0];
                float a = 1.f / (1.f + expf(-alpha[0]));
                score[grow] = a * rer[grow] + (1.f - a) * gnn;
            }
        } else {
#pragma unroll
            for (int cc = 0; cc < 4; cc++)
                outp[(size_t)grow * D + cc * 32 + lane] = v[cc];
        }
    }
}

// ---------------- launch ----------------
extern "C" void kernel_launch(void* const* d_in, const int* in_sizes, int n_in,
                              void* d_out, int out_size) {
    const float* x       = (const float*)d_in[0];
    const int*   ei      = (const int*)  d_in[1];
    const float* rer     = (const float*)d_in[2];
    const float* proj_w  = (const float*)d_in[3];
    const float* proj_b  = (const float*)d_in[4];
    const float* lin_l_w = (const float*)d_in[5];
    const float* lin_l_b = (const float*)d_in[6];
    const float* lin_r_w = (const float*)d_in[7];
    const float* ln_g    = (const float*)d_in[8];
    const float* ln_b    = (const float*)d_in[9];
    const float* head_w  = (const float*)d_in[10];
    const float* head_b  = (const float*)d_in[11];
    const float* alpha   = (const float*)d_in[12];

    int N = in_sizes[0] / D;
    int E = in_sizes[1] / 2;
    const int* src = ei;
    const int* dst = ei + E;
    float* out = (float*)d_out;

    float *res, *agg, *h0, *h1, *invdeg;
    int *deg, *rowptr, *cursor, *stmp, *blks, *srcs;
    __nv_bfloat16 *whi, *wlo;
    cudaGetSymbolAddress((void**)&res,    g_res);
    cudaGetSymbolAddress((void**)&agg,    g_agg);
    cudaGetSymbolAddress((void**)&h0,     g_h0);
    cudaGetSymbolAddress((void**)&h1,     g_h1);
    cudaGetSymbolAddress((void**)&invdeg, g_invdeg);
    cudaGetSymbolAddress((void**)&deg,    g_deg);
    cudaGetSymbolAddress((void**)&rowptr, g_rowptr);
    cudaGetSymbolAddress((void**)&cursor, g_cursor);
    cudaGetSymbolAddress((void**)&stmp,   g_scantmp);
    cudaGetSymbolAddress((void**)&blks,   g_blksums);
    cudaGetSymbolAddress((void**)&srcs,   g_srcsorted);
    cudaGetSymbolAddress((void**)&whi,    g_whi);
    cudaGetSymbolAddress((void**)&wlo,    g_wlo);

    int nb = (N + 1023) / 1024;

    // CSR build + weight split
    k_zero <<<(N + 255) / 256, 256>>>(deg, rowptr, N);
    k_count<<<(E + 255) / 256, 256>>>(dst, deg, E);
    k_scan1<<<nb, 1024>>>(deg, stmp, blks, N);
    k_scan2<<<1, 32>>>(blks, nb);
    k_scan3<<<nb, 1024>>>(stmp, blks, rowptr, N);
    k_prep <<<(N + 255) / 256, 256>>>(rowptr, deg, cursor, invdeg, N);
    k_fill <<<(E + 255) / 256, 256>>>(src, dst, cursor, srcs, E);
    k_wsplit<<<(7 * 16384 + 255) / 256, 256>>>(proj_w, lin_l_w, lin_r_w, whi, wlo);

    cudaFuncSetAttribute(k_tcgemm, cudaFuncAttributeMaxDynamicSharedMemorySize, SMEM_BYTES);

    int blocks = (N + TILE_M - 1) / TILE_M;
    int warp_blocks = (N + 7) / 8;
    const size_t WM = 128 * 128;   // elements per weight matrix

    // residual = x @ proj_w^T + proj_b     (single pass, no LN)
    k_tcgemm<<<blocks, THREADS, SMEM_BYTES>>>(
        x, nullptr, whi, wlo, nullptr, nullptr, proj_b,
        nullptr, nullptr, nullptr, res,
        nullptr, nullptr, nullptr, nullptr, nullptr, N);

    const float* h_cur = x;
    float* bufs[2] = {h0, h1};
    for (int i = 0; i < 3; i++) {
        float* h_next = bufs[i & 1];
        bool last = (i == 2);
        k_aggregate<<<warp_blocks, 256>>>(h_cur, rowptr, srcs, invdeg, agg, N);
        k_tcgemm<<<blocks, THREADS, SMEM_BYTES>>>(
            agg, h_cur,
            whi + (1 + i) * WM, wlo + (1 + i) * WM,
            whi + (4 + i) * WM, wlo + (4 + i) * WM,
            lin_l_b + (size_t)i * D,
            ln_g + (size_t)i * D, ln_b + (size_t)i * D,
            (i == 0) ? res : h_cur,
            last ? nullptr : h_next,
            last ? head_w : nullptr,
            last ? head_b : nullptr,
            last ? rer    : nullptr,
            last ? alpha  : nullptr,
            last ? out    : nullptr, N);
        h_cur = h_next;
    }
}